// round 17
// baseline (speedup 1.0000x reference)
#include <cuda_runtime.h>
#include <cstdint>

#define CAND 512           // candidate buffer entries (u64)
#define TBL  1024          // bins per table
#define XSCALE 51.2f       // TBL / 20  (range [-10, 10])
#define XOFF   512.0f      // 10 * XSCALE
#define THRESH0 2.7f       // prefilter threshold (fallback makes any value correct)
#define FULLM 0xFFFFFFFFu

static __device__ float g_rowsum[8192];
static __device__ float g_table[2 * TBL];          // [0..TBL)=f_neg, [TBL..2TBL)=f_pos
static __device__ unsigned char g_catbit[16384];   // (1<<(cat-1))&7
static __device__ int   g_clist[16384];            // (c<<3)|catbit for catbit!=0
static __device__ int   g_ncl = 0;                 // list length (reset each launch)
static __device__ int   g_count = 0;

// ---------------------------------------------------------------------------
__device__ __forceinline__ unsigned sortkey32(float x) {
    unsigned u = __float_as_uint(x);
    return u ^ ((unsigned)(((int)u) >> 31) | 0x80000000u);
}
__device__ __forceinline__ unsigned long long makekey(unsigned k32, int c) {
    return ((unsigned long long)k32 << 32) |
           (unsigned long long)(0xFFFFFFFFu - (unsigned)c);
}
// saturating index: negatives clamp to 0 in the F2I itself
__device__ __forceinline__ int tbl_idx(float xv) {
    unsigned j = __float2uint_rz(fmaf(xv, XSCALE, XOFF));
    return (int)umin(j, (unsigned)(TBL - 1));
}
// exact select of table half: y in {0.0f, 1.0f}; 0x3F800000>>13 & 0x400 == TBL
__device__ __forceinline__ int pos_off(float yv) {
    return (int)((__float_as_uint(yv) >> 13) & (unsigned)TBL);
}

// ---------------------------------------------------------------------------
// Kernel 0: build loss tables (exact math) + catbit LUT + whitelist class list.
// ---------------------------------------------------------------------------
__global__ void asl_build(const int* __restrict__ cat, int C)
{
    int j = blockIdx.x * 256 + threadIdx.x;
    if (j < 2 * TBL) {
        bool pos = j >= TBL;
        int  q   = pos ? j - TBL : j;
        float x  = (q + 0.5f) * (20.0f / TBL) - 10.0f;
        float sp = 1.0f / (1.0f + expf(-x));
        float v;
        if (pos) {
            v = logf(fmaxf(sp, 1e-8f)) * (1.0f - sp);
        } else {
            float pv = fminf(1.05f - sp, 1.0f);
            float om = 1.0f - pv;
            float om2 = om * om;
            v = logf(fmaxf(pv, 1e-8f)) * om2 * om2;
        }
        g_table[j] = v;
    }
    int c = j - 2 * TBL;
    if (c >= 0 && c < C) {
        unsigned char cb = (unsigned char)((1 << (cat[c] - 1)) & 7);
        g_catbit[c] = cb;
        if (cb) {                       // compact whitelist classes (~1% of C)
            int q = atomicAdd(&g_ncl, 1);
            g_clist[q] = (c << 3) | (int)cb;
        }
    }
}

// ---------------------------------------------------------------------------
// Kernel 1: 2 rows per block; register-prefetch hot loop; flags via class list.
// ---------------------------------------------------------------------------
__global__ void __launch_bounds__(256, 7)
asl_row_kernel(const float* __restrict__ X,
               const float* __restrict__ Y,
               const int*   __restrict__ cat,
               const unsigned char* __restrict__ inmap,
               int C, int B, float* __restrict__ out)
{
    const int tid  = threadIdx.x;
    const int lane = tid & 31;
    const int warp = tid >> 5;

    __shared__ float s_tbl[2 * TBL];              // 8 KB
    __shared__ unsigned long long s_buf[CAND];    // 4 KB
    __shared__ unsigned long long s_top[10];
    __shared__ float s_sumw[8];
    __shared__ int s_flags, s_cnt, s_last;

    {   // table L2 -> smem (once per block, amortized over 2 rows)
        const float4* gt = (const float4*)g_table;
        float4* st = (float4*)s_tbl;
#pragma unroll
        for (int i = tid; i < (2 * TBL) / 4; i += 256) st[i] = gt[i];
    }
    const int ncl = g_ncl;
    __syncthreads();

    for (int row = blockIdx.x; row < B; row += gridDim.x) {
        if (tid == 0) { s_flags = 0; s_cnt = 0; }
        __syncthreads();

        const float* __restrict__ xr = X + (size_t)row * C;
        const float* __restrict__ yr = Y + (size_t)row * C;

        float sum0 = 0.0f, sum1 = 0.0f;

        // ---- whitelist flags: only classes with catbit != 0 (~1% of C) ----
        {
            int fl = 0;
            for (int i = tid; i < ncl; i += 256) {
                const int e = g_clist[i];
                if (yr[e >> 3] != 0.0f) fl |= (e & 7);
            }
            if (fl) atomicOr(&s_flags, fl);
        }

        // alignment: first element index whose address is 16B aligned
        const int p = (int)((4 - (((size_t)row * (size_t)C) & 3)) & 3);
        const int nv = (C - p) >> 2;
        const int t0 = p + (nv << 2);

        // prologue + tail (<=3 elements each)
        for (int c = tid; c < p; c += 256) {
            const float xv = xr[c];
            sum0 += s_tbl[tbl_idx(xv) + pos_off(yr[c])];
            if (xv > THRESH0) {
                int q = atomicAdd(&s_cnt, 1);
                if (q < CAND) s_buf[q] = makekey(sortkey32(xv), c);
            }
        }
        for (int c = t0 + tid; c < C; c += 256) {
            const float xv = xr[c];
            sum0 += s_tbl[tbl_idx(xv) + pos_off(yr[c])];
            if (xv > THRESH0) {
                int q = atomicAdd(&s_cnt, 1);
                if (q < CAND) s_buf[q] = makekey(sortkey32(xv), c);
            }
        }

        // ---- main streaming loop with 1-deep register prefetch ----
        const float4* __restrict__ x4 = (const float4*)(xr + p);
        const float4* __restrict__ y4 = (const float4*)(yr + p);

        int v = tid;
        float4 xq, yq;
        if (v < nv) { xq = __ldcs(x4 + v); yq = __ldcs(y4 + v); }
        while (v < nv) {
            const int vn = v + 256;
            float4 xn, yn;
            if (vn < nv) { xn = __ldcs(x4 + vn); yn = __ldcs(y4 + vn); }

            sum0 += s_tbl[tbl_idx(xq.x) + pos_off(yq.x)];
            sum1 += s_tbl[tbl_idx(xq.y) + pos_off(yq.y)];
            sum0 += s_tbl[tbl_idx(xq.z) + pos_off(yq.z)];
            sum1 += s_tbl[tbl_idx(xq.w) + pos_off(yq.w)];

            // collect gate (fires ~36% of warp-iterations)
            const float xm = fmaxf(fmaxf(xq.x, xq.y), fmaxf(xq.z, xq.w));
            if (xm > THRESH0) {
                const int c0 = p + (v << 2);
                if (xq.x > THRESH0) { int q = atomicAdd(&s_cnt, 1); if (q < CAND) s_buf[q] = makekey(sortkey32(xq.x), c0 + 0); }
                if (xq.y > THRESH0) { int q = atomicAdd(&s_cnt, 1); if (q < CAND) s_buf[q] = makekey(sortkey32(xq.y), c0 + 1); }
                if (xq.z > THRESH0) { int q = atomicAdd(&s_cnt, 1); if (q < CAND) s_buf[q] = makekey(sortkey32(xq.z), c0 + 2); }
                if (xq.w > THRESH0) { int q = atomicAdd(&s_cnt, 1); if (q < CAND) s_buf[q] = makekey(sortkey32(xq.w), c0 + 3); }
            }

            v = vn; xq = xn; yq = yn;
        }

        // ---- reduce sum ----
        float sum = sum0 + sum1;
#pragma unroll
        for (int off = 16; off; off >>= 1)
            sum += __shfl_down_sync(FULLM, sum, off);
        if (lane == 0) s_sumw[warp] = sum;
        __syncthreads();

        // ---- resolve exact top-10 (fast path: 10 <= n <= CAND first try) ----
        float thF = THRESH0;
        unsigned long long thK = 0ULL;
        bool useKey = false;
        int iter = 0;
        for (;;) {
            const int n = s_cnt;
            const bool done = (n >= 10 && n <= CAND) || iter >= 32;
            if (done || n > CAND) {
                if (warp == 0) {
                    const int m = min(n, CAND);
                    for (int kk = 0; kk < 10; ++kk) {
                        unsigned long long vv = 0ULL;
                        for (int i = lane; i < m; i += 32) {
                            unsigned long long b = s_buf[i];
                            if (b > vv) vv = b;
                        }
#pragma unroll
                        for (int off = 16; off; off >>= 1) {
                            unsigned long long o = __shfl_down_sync(FULLM, vv, off);
                            if (o > vv) vv = o;
                        }
                        unsigned long long w = __shfl_sync(FULLM, vv, 0);
                        if (lane == 0) s_top[kk] = w;
                        for (int i = lane; i < m; i += 32)
                            if (s_buf[i] == w) s_buf[i] = 0ULL;
                    }
                }
                __syncthreads();
                if (done) break;
                thK = s_top[9];
                useKey = true;        // recollect with key >= thK (>=10 guaranteed)
            } else {
                thF -= 4.0f;          // too few: lower the float threshold
                useKey = false;
            }
            __syncthreads();
            if (tid == 0) s_cnt = 0;
            __syncthreads();
            for (int c = tid; c < C; c += 256) {
                const float xv = xr[c];
                if (useKey) {
                    unsigned long long key = makekey(sortkey32(xv), c);
                    if (key >= thK) {
                        int q = atomicAdd(&s_cnt, 1);
                        if (q < CAND) s_buf[q] = key;
                    }
                } else if (xv > thF) {
                    int q = atomicAdd(&s_cnt, 1);
                    if (q < CAND) s_buf[q] = makekey(sortkey32(xv), c);
                }
            }
            __syncthreads();
            ++iter;
        }

        // ---- correction for the top-10 elements (exact math) ----
        const int fl = s_flags;
        const bool p1 = (fl & 1) != 0, p2 = (fl & 2) != 0, p3 = (fl & 4) != 0;
        const bool has4 = !(p1 | p2 | p3);

        float delta = 0.0f;
        if (tid < 10 && s_top[tid] != 0ULL) {
            const unsigned idx = 0xFFFFFFFFu - (unsigned)(s_top[tid] & 0xFFFFFFFFull);
            const float xv = xr[idx];
            const float yv = yr[idx];
            const float sp = __fdividef(1.0f, 1.0f + __expf(-xv));
            const float sn = fminf(1.05f - sp, 1.0f);
            const bool  pos = (yv != 0.0f);
            const float pv  = pos ? sp : sn;
            const float l   = __logf(fmaxf(pv, 1e-8f));
            const float om  = 1.0f - pv;
            const float om2 = om * om;
            const float w   = pos ? om : om2 * om2;

            const int  cv  = cat[idx];
            const bool inm = inmap[idx] != 0;
            const bool condA = (!inm) && has4;
            const bool condB = (cv == 1 && p1) || (cv == 2 && p2) ||
                               (cv == 3 && p3) || (cv == 4 && has4);
            if (condA || condB) {
                const float factor = (pos ? sn : sp) * 2.0f;   // ALPHA3 = 2
                delta = l * w * (factor - 1.0f);
            }
        }
        if (warp == 0) {
#pragma unroll
            for (int off = 16; off; off >>= 1)
                delta += __shfl_down_sync(FULLM, delta, off);
        }
        if (tid == 0) {
            float tot = delta;
#pragma unroll
            for (int i = 0; i < 8; ++i) tot += s_sumw[i];
            g_rowsum[row] = tot;
        }
        __syncthreads();   // protect s_buf/s_cnt/s_top before next row resets
    }

    // ---- last-block finalize: deterministic double reduction + resets ----
    __threadfence();
    if (tid == 0) s_last = (atomicAdd(&g_count, 1) == gridDim.x - 1) ? 1 : 0;
    __syncthreads();
    if (s_last) {
        __threadfence();
        double* sd = (double*)s_buf;
        double acc = 0.0;
        for (int i = tid; i < B; i += 256) acc += (double)g_rowsum[i];
        sd[tid] = acc;
        __syncthreads();
#pragma unroll
        for (int off = 128; off; off >>= 1) {
            if (tid < off) sd[tid] += sd[tid + off];
            __syncthreads();
        }
        if (tid == 0) {
            out[0] = -(float)sd[0];
            g_count = 0;
            g_ncl = 0;     // next launch's build kernel re-compacts from 0
        }
    }
}

extern "C" void kernel_launch(void* const* d_in, const int* in_sizes, int n_in,
                              void* d_out, int out_size)
{
    const float*         X   = (const float*)d_in[0];
    const float*         Y   = (const float*)d_in[1];
    const int*           cat = (const int*)d_in[2];
    const unsigned char* inm = (const unsigned char*)d_in[3];

    const int C = in_sizes[2];        // per-class arrays -> 9605
    const int B = in_sizes[0] / C;    // 2048

    int grid = (B + 1) / 2;           // 2 rows per block, single resident wave
    if (grid < 1) grid = 1;

    asl_build<<<(2 * TBL + C + 255) / 256, 256>>>(cat, C);
    asl_row_kernel<<<grid, 256>>>(X, Y, cat, inm, C, B, (float*)d_out);
}